// round 6
// baseline (speedup 1.0000x reference)
#include <cuda_runtime.h>
#include <cstdint>

// ImplicitFunction: hidden 64x64 layers via mma.sync bf16 m16n8k16, 3-term
// hi/lo split. Round-6: 32 rows/warp + 1 CTA/SM (halves weight LDS per point
// vs round 5) AND 3-pass MMA scheduling with 16 independent MMAs per pass
// (dep-distance fix from round 5). Best of both prior rounds.

#define NT 256
#define TILE_M 256          // 8 warps * 32 rows
#define NEG 0.2f
#define NLAYER 6

// ---- SMEM layout (byte offsets) ----
#define OFF_WF   0
#define WF_BYTES (NLAYER * 8 * 4 * 32 * 16)   // 98304
#define OFF_SH   (OFF_WF + WF_BYTES)
#define OFF_BH   (OFF_SH + 1536)
#define OFF_W0   (OFF_BH + 1536)
#define OFF_S0   (OFF_W0 + 768)
#define OFF_B0   (OFF_S0 + 256)
#define OFF_WO   (OFF_B0 + 256)
#define OFF_SOBO (OFF_WO + 256)
#define SMEM_BYTES (OFF_SOBO + 16)

__device__ __align__(16) uint32_t g_wfrag[NLAYER * 8 * 4 * 32 * 4];

static __device__ __forceinline__ float lrelu(float t) { return fmaxf(t, NEG * t); }

static __device__ __forceinline__ uint32_t pack_bf16x2(float a, float b) {
    uint32_t r;
    asm("cvt.rn.bf16x2.f32 %0, %1, %2;" : "=r"(r) : "f"(b), "f"(a));
    return r;
}
static __device__ __forceinline__ uint32_t split2(float a, float b, uint32_t* lo) {
    uint32_t hi = pack_bf16x2(a, b);
    float ha = __uint_as_float(hi << 16);
    float hb = __uint_as_float(hi & 0xFFFF0000u);
    *lo = pack_bf16x2(a - ha, b - hb);
    return hi;
}
static __device__ __forceinline__ void mma_bf16(float* c, const uint32_t* a,
                                                uint32_t b0, uint32_t b1) {
    asm volatile(
        "mma.sync.aligned.m16n8k16.row.col.f32.bf16.bf16.f32 "
        "{%0,%1,%2,%3}, {%4,%5,%6,%7}, {%8,%9}, {%0,%1,%2,%3};"
        : "+f"(c[0]), "+f"(c[1]), "+f"(c[2]), "+f"(c[3])
        : "r"(a[0]), "r"(a[1]), "r"(a[2]), "r"(a[3]), "r"(b0), "r"(b1));
}

// prep: weights -> hi/lo bf16 fragment order
__global__ void prep_weights(const float* __restrict__ wh) {
    int t = blockIdx.x * blockDim.x + threadIdx.x;
    if (t >= NLAYER * 8 * 4 * 32) return;
    int lane = t & 31;
    int kt = (t >> 5) & 3;
    int nt = (t >> 7) & 7;
    int l = t >> 10;
    int k0 = kt * 16 + (lane & 3) * 2;
    int nn = nt * 8 + (lane >> 2);
    const float* W = wh + l * 4096;
    float w0 = W[k0 * 64 + nn];
    float w1 = W[(k0 + 1) * 64 + nn];
    float w2 = W[(k0 + 8) * 64 + nn];
    float w3 = W[(k0 + 9) * 64 + nn];
    uint32_t l0, l1;
    uint32_t h0 = split2(w0, w1, &l0);
    uint32_t h1 = split2(w2, w3, &l1);
    ((uint4*)g_wfrag)[t] = make_uint4(h0, h1, l0, l1);
}

__global__ __launch_bounds__(NT, 1)
void implicit_mlp_mma(const float* __restrict__ points,
                      const float* __restrict__ w0,
                      const float* __restrict__ s0,
                      const float* __restrict__ b0,
                      const float* __restrict__ sh,
                      const float* __restrict__ bh,
                      const float* __restrict__ wo,
                      const float* __restrict__ so,
                      const float* __restrict__ bo,
                      float* __restrict__ out,
                      int n, int ntiles)
{
    extern __shared__ __align__(16) unsigned char smem[];

    const int tid = threadIdx.x;
    const int wid = tid >> 5;
    const int lane = tid & 31;
    const int tig = lane & 3;
    const int grp = lane >> 2;
    const int cb = tig * 2;

    {
        const uint4* gsrc = (const uint4*)g_wfrag;
        uint4* gdst = (uint4*)(smem + OFF_WF);
        for (int i = tid; i < WF_BYTES / 16; i += NT) gdst[i] = gsrc[i];
        float* d;
        d = (float*)(smem + OFF_SH); for (int i = tid; i < 384; i += NT) d[i] = sh[i];
        d = (float*)(smem + OFF_BH); for (int i = tid; i < 384; i += NT) d[i] = bh[i];
        d = (float*)(smem + OFF_W0); for (int i = tid; i < 192; i += NT) d[i] = w0[i];
        d = (float*)(smem + OFF_S0); if (tid < 64) d[tid] = s0[tid];
        d = (float*)(smem + OFF_B0); if (tid < 64) d[tid] = b0[tid];
        d = (float*)(smem + OFF_WO); if (tid < 64) d[tid] = wo[tid];
        if (tid == 0) {
            ((float*)(smem + OFF_SOBO))[0] = so[0];
            ((float*)(smem + OFF_SOBO))[1] = bo[0];
        }
    }
    __syncthreads();

    const float* shm_sh = (const float*)(smem + OFF_SH);
    const float* shm_bh = (const float*)(smem + OFF_BH);
    const float* shm_w0 = (const float*)(smem + OFF_W0);
    const float* shm_s0 = (const float*)(smem + OFF_S0);
    const float* shm_b0 = (const float*)(smem + OFF_B0);
    const float* shm_wo = (const float*)(smem + OFF_WO);
    const float so_v = ((const float*)(smem + OFF_SOBO))[0];
    const float bo_v = ((const float*)(smem + OFF_SOBO))[1];
    const uint4* wf_sh = (const uint4*)(smem + OFF_WF);

    for (int tile = blockIdx.x; tile < ntiles; tile += gridDim.x) {
        const long long rowbase = (long long)tile * TILE_M + wid * 32;

        float acc[2][8][4];
        uint32_t Ahi[2][4][4], Alo[2][4][4];

        // ---- layer 0 (K=3) scalar ----
#pragma unroll
        for (int mt = 0; mt < 2; mt++) {
            const long long r0 = rowbase + mt * 16 + grp;
            const long long r1 = r0 + 8;
            float p0x = 0.f, p0y = 0.f, p0z = 0.f, p1x = 0.f, p1y = 0.f, p1z = 0.f;
            if (r0 < n) { p0x = points[r0*3+0]; p0y = points[r0*3+1]; p0z = points[r0*3+2]; }
            if (r1 < n) { p1x = points[r1*3+0]; p1y = points[r1*3+1]; p1z = points[r1*3+2]; }
#pragma unroll
            for (int nt = 0; nt < 8; nt++) {
#pragma unroll
                for (int j = 0; j < 2; j++) {
                    int c = nt * 8 + cb + j;
                    float wa = shm_w0[c], wb = shm_w0[64 + c], wc = shm_w0[128 + c];
                    float sv = shm_s0[c], bv = shm_b0[c];
                    acc[mt][nt][j]     = lrelu(fmaf(fmaf(p0x, wa, fmaf(p0y, wb, p0z * wc)), sv, bv));
                    acc[mt][nt][2 + j] = lrelu(fmaf(fmaf(p1x, wa, fmaf(p1y, wb, p1z * wc)), sv, bv));
                }
            }
        }
#pragma unroll
        for (int mt = 0; mt < 2; mt++)
#pragma unroll
            for (int kt = 0; kt < 4; kt++) {
                Ahi[mt][kt][0] = split2(acc[mt][2*kt][0],   acc[mt][2*kt][1],   &Alo[mt][kt][0]);
                Ahi[mt][kt][1] = split2(acc[mt][2*kt][2],   acc[mt][2*kt][3],   &Alo[mt][kt][1]);
                Ahi[mt][kt][2] = split2(acc[mt][2*kt+1][0], acc[mt][2*kt+1][1], &Alo[mt][kt][2]);
                Ahi[mt][kt][3] = split2(acc[mt][2*kt+1][2], acc[mt][2*kt+1][3], &Alo[mt][kt][3]);
            }

        // ---- 6 hidden layers: per kt, 3 passes of 16 independent MMAs ----
#pragma unroll
        for (int l = 0; l < NLAYER; l++) {
#pragma unroll
            for (int mt = 0; mt < 2; mt++)
#pragma unroll
                for (int nt = 0; nt < 8; nt++)
#pragma unroll
                    for (int e = 0; e < 4; e++) acc[mt][nt][e] = 0.f;

            const uint4* wl = wf_sh + l * 1024 + lane;
#pragma unroll
            for (int kt = 0; kt < 4; kt++) {
                uint4 wf[8];
#pragma unroll
                for (int nt = 0; nt < 8; nt++) wf[nt] = wl[(nt * 4 + kt) * 32];
                // pass 1: hi*hi — 16 independent MMAs
#pragma unroll
                for (int nt = 0; nt < 8; nt++) {
                    mma_bf16(acc[0][nt], Ahi[0][kt], wf[nt].x, wf[nt].y);
                    mma_bf16(acc[1][nt], Ahi[1][kt], wf[nt].x, wf[nt].y);
                }
                // pass 2: hi*lo
#pragma unroll
                for (int nt = 0; nt < 8; nt++) {
                    mma_bf16(acc[0][nt], Ahi[0][kt], wf[nt].z, wf[nt].w);
                    mma_bf16(acc[1][nt], Ahi[1][kt], wf[nt].z, wf[nt].w);
                }
                // pass 3: lo*hi
#pragma unroll
                for (int nt = 0; nt < 8; nt++) {
                    mma_bf16(acc[0][nt], Alo[0][kt], wf[nt].x, wf[nt].y);
                    mma_bf16(acc[1][nt], Alo[1][kt], wf[nt].x, wf[nt].y);
                }
            }

            const float* sl = shm_sh + l * 64;
            const float* bl = shm_bh + l * 64;
            if (l < NLAYER - 1) {
#pragma unroll
                for (int mt = 0; mt < 2; mt++)
#pragma unroll
                    for (int nt = 0; nt < 8; nt++) {
                        int c0 = nt * 8 + cb;
                        float s0v = sl[c0], s1v = sl[c0 + 1];
                        float b0v = bl[c0], b1v = bl[c0 + 1];
                        acc[mt][nt][0] = lrelu(fmaf(acc[mt][nt][0], s0v, b0v));
                        acc[mt][nt][1] = lrelu(fmaf(acc[mt][nt][1], s1v, b1v));
                        acc[mt][nt][2] = lrelu(fmaf(acc[mt][nt][2], s0v, b0v));
                        acc[mt][nt][3] = lrelu(fmaf(acc[mt][nt][3], s1v, b1v));
                    }
#pragma unroll
                for (int mt = 0; mt < 2; mt++)
#pragma unroll
                    for (int kt = 0; kt < 4; kt++) {
                        Ahi[mt][kt][0] = split2(acc[mt][2*kt][0],   acc[mt][2*kt][1],   &Alo[mt][kt][0]);
                        Ahi[mt][kt][1] = split2(acc[mt][2*kt][2],   acc[mt][2*kt][3],   &Alo[mt][kt][1]);
                        Ahi[mt][kt][2] = split2(acc[mt][2*kt+1][0], acc[mt][2*kt+1][1], &Alo[mt][kt][2]);
                        Ahi[mt][kt][3] = split2(acc[mt][2*kt+1][2], acc[mt][2*kt+1][3], &Alo[mt][kt][3]);
                    }
            } else {
#pragma unroll
                for (int mt = 0; mt < 2; mt++) {
                    float d0 = 0.f, d1 = 0.f;
#pragma unroll
                    for (int nt = 0; nt < 8; nt++) {
                        int c0 = nt * 8 + cb;
                        float s0v = sl[c0], s1v = sl[c0 + 1];
                        float b0v = bl[c0], b1v = bl[c0 + 1];
                        float w0v = shm_wo[c0], w1v = shm_wo[c0 + 1];
                        d0 = fmaf(lrelu(fmaf(acc[mt][nt][0], s0v, b0v)), w0v, d0);
                        d0 = fmaf(lrelu(fmaf(acc[mt][nt][1], s1v, b1v)), w1v, d0);
                        d1 = fmaf(lrelu(fmaf(acc[mt][nt][2], s0v, b0v)), w0v, d1);
                        d1 = fmaf(lrelu(fmaf(acc[mt][nt][3], s1v, b1v)), w1v, d1);
                    }
                    d0 += __shfl_xor_sync(0xffffffffu, d0, 1);
                    d0 += __shfl_xor_sync(0xffffffffu, d0, 2);
                    d1 += __shfl_xor_sync(0xffffffffu, d1, 1);
                    d1 += __shfl_xor_sync(0xffffffffu, d1, 2);
                    if (tig == 0) {
                        long long r0 = rowbase + mt * 16 + grp;
                        long long r1 = r0 + 8;
                        if (r0 < n) out[r0] = fmaf(d0, so_v, bo_v);
                        if (r1 < n) out[r1] = fmaf(d1, so_v, bo_v);
                    }
                }
            }
        }
    }
}

extern "C" void kernel_launch(void* const* d_in, const int* in_sizes, int n_in,
                              void* d_out, int out_size)
{
    const float* points = (const float*)d_in[0];
    const float* w0     = (const float*)d_in[1];
    const float* s0     = (const float*)d_in[2];
    const float* b0     = (const float*)d_in[3];
    const float* wh     = (const float*)d_in[4];
    const float* sh     = (const float*)d_in[5];
    const float* bh     = (const float*)d_in[6];
    const float* wo     = (const float*)d_in[7];
    const float* so     = (const float*)d_in[8];
    const float* bo     = (const float*)d_in[9];
    float* out = (float*)d_out;

    const int n = in_sizes[0] / 3;
    const int ntiles = (n + TILE_M - 1) / TILE_M;

    prep_weights<<<(NLAYER * 8 * 4 * 32 + 255) / 256, 256>>>(wh);

    int sms = 148;
    cudaDeviceGetAttribute(&sms, cudaDevAttrMultiProcessorCount, 0);
    cudaFuncSetAttribute(implicit_mlp_mma,
                         cudaFuncAttributeMaxDynamicSharedMemorySize, SMEM_BYTES);
    int grid = sms < ntiles ? sms : ntiles;

    implicit_mlp_mma<<<grid, NT, SMEM_BYTES>>>(
        points, w0, s0, b0, sh, bh, wo, so, bo, out, n, ntiles);
}

// round 7
// speedup vs baseline: 1.0290x; 1.0290x over previous
#include <cuda_runtime.h>
#include <cstdint>

// ImplicitFunction: hidden 64x64 layers via mma.sync bf16 m16n8k16, 3-term
// hi/lo split. Round-7: the two m16 row-streams per warp are scheduled as
// independent pipelines. Per layer, a shared kt-loop loads weight fragments
// once and interleaves each stream's (previous-layer) epilogue chunk between
// MMA passes, so the tensor queue always has pending HMMAs while scalar
// epilogue work issues. Previous-layer accumulators live in ping-pong
// buffers; A-fragments are transient (one kt iteration).

#define NT 256
#define TILE_M 256          // 8 warps * 32 rows
#define NEG 0.2f
#define NLAYER 6

#define OFF_WF   0
#define WF_BYTES (NLAYER * 8 * 4 * 32 * 16)   // 98304
#define OFF_SH   (OFF_WF + WF_BYTES)
#define OFF_BH   (OFF_SH + 1536)
#define OFF_W0   (OFF_BH + 1536)
#define OFF_S0   (OFF_W0 + 768)
#define OFF_B0   (OFF_S0 + 256)
#define OFF_WO   (OFF_B0 + 256)
#define OFF_SOBO (OFF_WO + 256)
#define SMEM_BYTES (OFF_SOBO + 16)

__device__ __align__(16) uint32_t g_wfrag[NLAYER * 8 * 4 * 32 * 4];

static __device__ __forceinline__ float lrelu(float t) { return fmaxf(t, NEG * t); }

static __device__ __forceinline__ uint32_t pack_bf16x2(float a, float b) {
    uint32_t r;
    asm("cvt.rn.bf16x2.f32 %0, %1, %2;" : "=r"(r) : "f"(b), "f"(a));
    return r;
}
static __device__ __forceinline__ uint32_t split2(float a, float b, uint32_t* lo) {
    uint32_t hi = pack_bf16x2(a, b);
    float ha = __uint_as_float(hi << 16);
    float hb = __uint_as_float(hi & 0xFFFF0000u);
    *lo = pack_bf16x2(a - ha, b - hb);
    return hi;
}
static __device__ __forceinline__ void mma_bf16(float* c, const uint32_t* a,
                                                uint32_t b0, uint32_t b1) {
    asm volatile(
        "mma.sync.aligned.m16n8k16.row.col.f32.bf16.bf16.f32 "
        "{%0,%1,%2,%3}, {%4,%5,%6,%7}, {%8,%9}, {%0,%1,%2,%3};"
        : "+f"(c[0]), "+f"(c[1]), "+f"(c[2]), "+f"(c[3])
        : "r"(a[0]), "r"(a[1]), "r"(a[2]), "r"(a[3]), "r"(b0), "r"(b1));
}

// prep: weights -> hi/lo bf16 fragment order
__global__ void prep_weights(const float* __restrict__ wh) {
    int t = blockIdx.x * blockDim.x + threadIdx.x;
    if (t >= NLAYER * 8 * 4 * 32) return;
    int lane = t & 31;
    int kt = (t >> 5) & 3;
    int nt = (t >> 7) & 7;
    int l = t >> 10;
    int k0 = kt * 16 + (lane & 3) * 2;
    int nn = nt * 8 + (lane >> 2);
    const float* W = wh + l * 4096;
    float w0 = W[k0 * 64 + nn];
    float w1 = W[(k0 + 1) * 64 + nn];
    float w2 = W[(k0 + 8) * 64 + nn];
    float w3 = W[(k0 + 9) * 64 + nn];
    uint32_t l0, l1;
    uint32_t h0 = split2(w0, w1, &l0);
    uint32_t h1 = split2(w2, w3, &l1);
    ((uint4*)g_wfrag)[t] = make_uint4(h0, h1, l0, l1);
}

// epilogue chunk (hidden layer L-1 output -> A fragments for k-tile kt)
static __device__ __forceinline__ void epi_chunk(
    const float (&aold)[8][4], uint32_t (&Fhi)[4], uint32_t (&Flo)[4],
    const float* sl, const float* bl, int cb, int kt)
{
    float e[2][4];
#pragma unroll
    for (int j = 0; j < 2; j++) {
        int nt = 2 * kt + j;
        int c0 = nt * 8 + cb;
        float s0v = sl[c0], s1v = sl[c0 + 1];
        float b0v = bl[c0], b1v = bl[c0 + 1];
        e[j][0] = lrelu(fmaf(aold[nt][0], s0v, b0v));
        e[j][1] = lrelu(fmaf(aold[nt][1], s1v, b1v));
        e[j][2] = lrelu(fmaf(aold[nt][2], s0v, b0v));
        e[j][3] = lrelu(fmaf(aold[nt][3], s1v, b1v));
    }
    Fhi[0] = split2(e[0][0], e[0][1], &Flo[0]);
    Fhi[1] = split2(e[0][2], e[0][3], &Flo[1]);
    Fhi[2] = split2(e[1][0], e[1][1], &Flo[2]);
    Fhi[3] = split2(e[1][2], e[1][3], &Flo[3]);
}

// layer-0 variant: aold already holds post-activation outputs; split only
static __device__ __forceinline__ void split_chunk(
    const float (&aold)[8][4], uint32_t (&Fhi)[4], uint32_t (&Flo)[4], int kt)
{
    Fhi[0] = split2(aold[2*kt][0],   aold[2*kt][1],   &Flo[0]);
    Fhi[1] = split2(aold[2*kt][2],   aold[2*kt][3],   &Flo[1]);
    Fhi[2] = split2(aold[2*kt+1][0], aold[2*kt+1][1], &Flo[2]);
    Fhi[3] = split2(aold[2*kt+1][2], aold[2*kt+1][3], &Flo[3]);
}

template <int L>
static __device__ __forceinline__ void layer_body(
    float (&o0)[8][4], float (&n0)[8][4],
    float (&o1)[8][4], float (&n1)[8][4],
    const uint4* wf_sh, int lane, int cb,
    const float* shm_sh, const float* shm_bh)
{
    const float* slp = shm_sh + (L > 0 ? (L - 1) : 0) * 64;
    const float* blp = shm_bh + (L > 0 ? (L - 1) : 0) * 64;
    const uint4* wl = wf_sh + L * 1024 + lane;

#pragma unroll
    for (int nt = 0; nt < 8; nt++)
#pragma unroll
        for (int e = 0; e < 4; e++) { n0[nt][e] = 0.f; n1[nt][e] = 0.f; }

#pragma unroll
    for (int kt = 0; kt < 4; kt++) {
        uint4 wf[8];
#pragma unroll
        for (int nt = 0; nt < 8; nt++) wf[nt] = wl[(nt * 4 + kt) * 32];

        // stream 0: epilogue chunk then 3 MMA passes (tensor queue stays fed)
        uint32_t F0hi[4], F0lo[4];
        if (L == 0) split_chunk(o0, F0hi, F0lo, kt);
        else        epi_chunk(o0, F0hi, F0lo, slp, blp, cb, kt);
#pragma unroll
        for (int nt = 0; nt < 8; nt++) mma_bf16(n0[nt], F0hi, wf[nt].x, wf[nt].y);
#pragma unroll
        for (int nt = 0; nt < 8; nt++) mma_bf16(n0[nt], F0hi, wf[nt].z, wf[nt].w);
#pragma unroll
        for (int nt = 0; nt < 8; nt++) mma_bf16(n0[nt], F0lo, wf[nt].x, wf[nt].y);

        // stream 1: its epilogue chunk issues while stream-0 HMMAs drain
        uint32_t F1hi[4], F1lo[4];
        if (L == 0) split_chunk(o1, F1hi, F1lo, kt);
        else        epi_chunk(o1, F1hi, F1lo, slp, blp, cb, kt);
#pragma unroll
        for (int nt = 0; nt < 8; nt++) mma_bf16(n1[nt], F1hi, wf[nt].x, wf[nt].y);
#pragma unroll
        for (int nt = 0; nt < 8; nt++) mma_bf16(n1[nt], F1hi, wf[nt].z, wf[nt].w);
#pragma unroll
        for (int nt = 0; nt < 8; nt++) mma_bf16(n1[nt], F1lo, wf[nt].x, wf[nt].y);
    }
}

__global__ __launch_bounds__(NT, 1)
void implicit_mlp_mma(const float* __restrict__ points,
                      const float* __restrict__ w0,
                      const float* __restrict__ s0,
                      const float* __restrict__ b0,
                      const float* __restrict__ sh,
                      const float* __restrict__ bh,
                      const float* __restrict__ wo,
                      const float* __restrict__ so,
                      const float* __restrict__ bo,
                      float* __restrict__ out,
                      int n, int ntiles)
{
    extern __shared__ __align__(16) unsigned char smem[];

    const int tid = threadIdx.x;
    const int wid = tid >> 5;
    const int lane = tid & 31;
    const int tig = lane & 3;
    const int grp = lane >> 2;
    const int cb = tig * 2;

    {
        const uint4* gsrc = (const uint4*)g_wfrag;
        uint4* gdst = (uint4*)(smem + OFF_WF);
        for (int i = tid; i < WF_BYTES / 16; i += NT) gdst[i] = gsrc[i];
        float* d;
        d = (float*)(smem + OFF_SH); for (int i = tid; i < 384; i += NT) d[i] = sh[i];
        d = (float*)(smem + OFF_BH); for (int i = tid; i < 384; i += NT) d[i] = bh[i];
        d = (float*)(smem + OFF_W0); for (int i = tid; i < 192; i += NT) d[i] = w0[i];
        d = (float*)(smem + OFF_S0); if (tid < 64) d[tid] = s0[tid];
        d = (float*)(smem + OFF_B0); if (tid < 64) d[tid] = b0[tid];
        d = (float*)(smem + OFF_WO); if (tid < 64) d[tid] = wo[tid];
        if (tid == 0) {
            ((float*)(smem + OFF_SOBO))[0] = so[0];
            ((float*)(smem + OFF_SOBO))[1] = bo[0];
        }
    }
    __syncthreads();

    const float* shm_sh = (const float*)(smem + OFF_SH);
    const float* shm_bh = (const float*)(smem + OFF_BH);
    const float* shm_w0 = (const float*)(smem + OFF_W0);
    const float* shm_s0 = (const float*)(smem + OFF_S0);
    const float* shm_b0 = (const float*)(smem + OFF_B0);
    const float* shm_wo = (const float*)(smem + OFF_WO);
    const float so_v = ((const float*)(smem + OFF_SOBO))[0];
    const float bo_v = ((const float*)(smem + OFF_SOBO))[1];
    const uint4* wf_sh = (const uint4*)(smem + OFF_WF);

    for (int tile = blockIdx.x; tile < ntiles; tile += gridDim.x) {
        const long long rowbase = (long long)tile * TILE_M + wid * 32;

        // ping-pong accumulators per stream
        float a0a[8][4], a0b[8][4], a1a[8][4], a1b[8][4];

        // ---- layer 0 (K=3) scalar: post-activation outputs into the 'a' buffers ----
        {
            const long long q0 = rowbase + grp;        // stream 0 rows
            const long long q1 = q0 + 8;
            const long long q2 = rowbase + 16 + grp;   // stream 1 rows
            const long long q3 = q2 + 8;
            float p0x=0.f,p0y=0.f,p0z=0.f, p1x=0.f,p1y=0.f,p1z=0.f;
            float p2x=0.f,p2y=0.f,p2z=0.f, p3x=0.f,p3y=0.f,p3z=0.f;
            if (q0 < n) { p0x=points[q0*3+0]; p0y=points[q0*3+1]; p0z=points[q0*3+2]; }
            if (q1 < n) { p1x=points[q1*3+0]; p1y=points[q1*3+1]; p1z=points[q1*3+2]; }
            if (q2 < n) { p2x=points[q2*3+0]; p2y=points[q2*3+1]; p2z=points[q2*3+2]; }
            if (q3 < n) { p3x=points[q3*3+0]; p3y=points[q3*3+1]; p3z=points[q3*3+2]; }
#pragma unroll
            for (int nt = 0; nt < 8; nt++) {
#pragma unroll
                for (int j = 0; j < 2; j++) {
                    int c = nt * 8 + cb + j;
                    float wa = shm_w0[c], wb = shm_w0[64 + c], wc = shm_w0[128 + c];
                    float sv = shm_s0[c], bv = shm_b0[c];
                    a0a[nt][j]   = lrelu(fmaf(fmaf(p0x,wa,fmaf(p0y,wb,p0z*wc)), sv, bv));
                    a0a[nt][2+j] = lrelu(fmaf(fmaf(p1x,wa,fmaf(p1y,wb,p1z*wc)), sv, bv));
                    a1a[nt][j]   = lrelu(fmaf(fmaf(p2x,wa,fmaf(p2y,wb,p2z*wc)), sv, bv));
                    a1a[nt][2+j] = lrelu(fmaf(fmaf(p3x,wa,fmaf(p3y,wb,p3z*wc)), sv, bv));
                }
            }
        }

        // ---- 6 hidden layers, ping-pong old/new ----
        layer_body<0>(a0a, a0b, a1a, a1b, wf_sh, lane, cb, shm_sh, shm_bh);
        layer_body<1>(a0b, a0a, a1b, a1a, wf_sh, lane, cb, shm_sh, shm_bh);
        layer_body<2>(a0a, a0b, a1a, a1b, wf_sh, lane, cb, shm_sh, shm_bh);
        layer_body<3>(a0b, a0a, a1b, a1a, wf_sh, lane, cb, shm_sh, shm_bh);
        layer_body<4>(a0a, a0b, a1a, a1b, wf_sh, lane, cb, shm_sh, shm_bh);
        layer_body<5>(a0b, a0a, a1b, a1a, wf_sh, lane, cb, shm_sh, shm_bh);
        // final pre-activations now in a0a (stream 0) and a1a (stream 1)

        // ---- output epilogue: lrelu(·*s5+b5) dot wo, lane reduce, store ----
        {
            const float* sl = shm_sh + 5 * 64;
            const float* bl = shm_bh + 5 * 64;
#pragma unroll
            for (int mt = 0; mt < 2; mt++) {
                float d0 = 0.f, d1 = 0.f;
#pragma unroll
                for (int nt = 0; nt < 8; nt++) {
                    int c0 = nt * 8 + cb;
                    float s0v = sl[c0], s1v = sl[c0 + 1];
                    float b0v = bl[c0], b1v = bl[c0 + 1];
                    float w0v = shm_wo[c0], w1v = shm_wo[c0 + 1];
                    const float* av = (mt == 0) ? a0a[nt] : a1a[nt];
                    d0 = fmaf(lrelu(fmaf(av[0], s0v, b0v)), w0v, d0);
                    d0 = fmaf(lrelu(fmaf(av[1], s1v, b1v)), w1v, d0);
                    d1 = fmaf(lrelu(fmaf(av[2], s0v, b0v)), w0v, d1);
                    d1 = fmaf(lrelu(fmaf(av[3], s1v, b1v)), w1v, d1);
                }
                d0 += __shfl_xor_sync(0xffffffffu, d0, 1);
                d0 += __shfl_xor_sync(0xffffffffu, d0, 2);
                d1 += __shfl_xor_sync(0xffffffffu, d1, 1);
                d1 += __shfl_xor_sync(0xffffffffu, d1, 2);
                if (tig == 0) {
                    long long r0 = rowbase + mt * 16 + grp;
                    long long r1 = r0 + 8;
                    if (r0 < n) out[r0] = fmaf(d0, so_v, bo_v);
                    if (r1 < n) out[r1] = fmaf(d1, so_v, bo_v);
                }
            }
        }
    }
}

extern "C" void kernel_launch(void* const* d_in, const int* in_sizes, int n_in,
                              void* d_out, int out_size)
{
    const float* points = (const float*)d_in[0];
    const float* w0     = (const float*)d_in[1];
    const float* s0     = (const float*)d_in[2];
    const float* b0     = (const float*)d_in[3];
    const float* wh     = (const float*)d_in[4];
    const float* sh     = (const float*)d_in[5];
    const float* bh     = (const float*)d_in[6];
    const float* wo     = (const float*)d_in[7];
    const float* so     = (const float*)d_in[8];
    const float* bo     = (const float*)d_in[9];
    float* out = (float*)d_out;

    const int n = in_sizes[0] / 3;
    const int ntiles = (n + TILE_M - 1) / TILE_M;

    prep_weights<<<(NLAYER * 8 * 4 * 32 + 255) / 256, 256>>>(wh);

    int sms = 148;
    cudaDeviceGetAttribute(&sms, cudaDevAttrMultiProcessorCount, 0);
    cudaFuncSetAttribute(implicit_mlp_mma,
                         cudaFuncAttributeMaxDynamicSharedMemorySize, SMEM_BYTES);
    int grid = sms < ntiles ? sms : ntiles;

    implicit_mlp_mma<<<grid, NT, SMEM_BYTES>>>(
        points, w0, s0, b0, sh, bh, wo, so, bo, out, n, ntiles);
}